// round 6
// baseline (speedup 1.0000x reference)
#include <cuda_runtime.h>

#define NN 8192
#define THREADS 512
#define NJ 16                      // j's per thread: 512*16 = 8192
#define GRID 296                   // 148 SMs * 2 CTAs -> one wave
#define ROWS_CAP 28                // ceil(NN/GRID) worst case
#define CTHREADS 1024
#define CPER (NN / CTHREADS)       // 8 rows per compaction thread

// Scratch (device globals; no allocation).
__device__ int   g_active[NN];     // compacted indices with event==1
__device__ int   g_M;              // number of active rows
__device__ float g_regsum;         // full regression sum
__device__ float g_rank[GRID];
__device__ float g_cnt[GRID];
__device__ unsigned int g_ticket;  // zero-init; reset by last block

// ---------------- Kernel 1: compaction + regression ----------------
__global__ void __launch_bounds__(CTHREADS)
svm_compact_kernel(const float* __restrict__ pred,
                   const float* __restrict__ target)
{
    const int t = threadIdx.x;

    int   idx_local[CPER];
    int   cnt = 0;
    float reg = 0.f;
    const int base = t * CPER;
    #pragma unroll
    for (int k = 0; k < CPER; ++k) {
        const int i = base + k;
        const float ti = target[2 * i];
        const float ei = target[2 * i + 1];
        const float pi = pred[i];
        float d = pi - ti;
        if (ei == 0.f) d = fmaxf(d, 0.f);
        reg = fmaf(d, d, reg);
        if (ei != 0.f) idx_local[cnt++] = i;
    }

    // Inclusive Hillis-Steele scan of per-thread counts (stable, i-ordered).
    __shared__ int s_cnt[CTHREADS];
    s_cnt[t] = cnt;
    __syncthreads();
    for (int off = 1; off < CTHREADS; off <<= 1) {
        const int v = (t >= off) ? s_cnt[t - off] : 0;
        __syncthreads();
        s_cnt[t] += v;
        __syncthreads();
    }
    const int excl = s_cnt[t] - cnt;
    for (int k = 0; k < cnt; ++k) g_active[excl + k] = idx_local[k];
    if (t == CTHREADS - 1) g_M = s_cnt[t];

    // Regression reduction (deterministic tree).
    __shared__ float s_reg[CTHREADS];
    s_reg[t] = reg;
    __syncthreads();
    for (int s = CTHREADS / 2; s > 0; s >>= 1) {
        if (t < s) s_reg[t] += s_reg[t + s];
        __syncthreads();
    }
    if (t == 0) g_regsum = s_reg[0];
}

// ---------------- Kernel 2: pairwise ranking + final combine ----------------
__global__ void __launch_bounds__(THREADS, 2)
svm_pair_kernel(const float* __restrict__ pred,
                const float* __restrict__ target,
                float* __restrict__ out)
{
    const int tid = threadIdx.x;
    const int bid = blockIdx.x;

    // Register-resident j data.
    float tj[NJ], pj[NJ];
    #pragma unroll
    for (int k = 0; k < NJ; ++k) {
        const int j = tid + k * THREADS;
        tj[k] = target[2 * j];
        pj[k] = pred[j];
    }

    const int M = g_M;

    // Preload this block's active rows into shared memory.
    __shared__ float s_ti[ROWS_CAP];
    __shared__ float s_pc[ROWS_CAP];   // 1 + p[i]
    if (tid < ROWS_CAP) {
        const int idx = bid + tid * GRID;
        if (idx < M) {
            const int i = g_active[idx];
            s_ti[tid] = target[2 * i];
            s_pc[tid] = 1.0f + pred[i];
        }
    }
    __syncthreads();

    const int nrows = (M > bid) ? (M - bid + GRID - 1) / GRID : 0;

    float r0 = 0.f, r1 = 0.f, r2 = 0.f, r3 = 0.f;
    int   c0 = 0, c1 = 0;

    for (int r = 0; r < nrows; ++r) {
        const float ti = s_ti[r];      // LDS broadcast
        const float c  = s_pc[r];
        #pragma unroll
        for (int k = 0; k < NJ; k += 4) {
            { const bool m = tj[k]   > ti; const float h = fmaxf(c - pj[k],   0.f); if (m) { r0 = fmaf(h, h, r0); c0++; } }
            { const bool m = tj[k+1] > ti; const float h = fmaxf(c - pj[k+1], 0.f); if (m) { r1 = fmaf(h, h, r1); c1++; } }
            { const bool m = tj[k+2] > ti; const float h = fmaxf(c - pj[k+2], 0.f); if (m) { r2 = fmaf(h, h, r2); c0++; } }
            { const bool m = tj[k+3] > ti; const float h = fmaxf(c - pj[k+3], 0.f); if (m) { r3 = fmaf(h, h, r3); c1++; } }
        }
    }

    const float rank_acc = (r0 + r1) + (r2 + r3);
    const int   cnt_acc  = c0 + c1;

    // Block reduction (deterministic tree).
    __shared__ float red_r[THREADS];
    __shared__ float red_c[THREADS];
    red_r[tid] = rank_acc;
    red_c[tid] = (float)cnt_acc;       // block sum < 2^24: exact
    __syncthreads();
    #pragma unroll
    for (int s = THREADS / 2; s > 0; s >>= 1) {
        if (tid < s) {
            red_r[tid] += red_r[tid + s];
            red_c[tid] += red_c[tid + s];
        }
        __syncthreads();
    }

    __shared__ bool s_last;
    if (tid == 0) {
        g_rank[bid] = red_r[0];
        g_cnt[bid]  = red_c[0];
        __threadfence();
        const unsigned int old = atomicAdd(&g_ticket, 1u);
        s_last = (old == GRID - 1);
    }
    __syncthreads();

    if (s_last) {
        __threadfence();
        __shared__ double sr[THREADS];
        __shared__ double sc[THREADS];
        double rank = 0.0, cnt = 0.0;
        if (tid < GRID) {              // 296 < 512
            rank = (double)g_rank[tid];
            cnt  = (double)g_cnt[tid];
        }
        sr[tid] = rank; sc[tid] = cnt;
        __syncthreads();
        #pragma unroll
        for (int s = THREADS / 2; s > 0; s >>= 1) {
            if (tid < s) {
                sr[tid] += sr[tid + s];
                sc[tid] += sc[tid + s];
            }
            __syncthreads();
        }
        if (tid == 0) {
            double c = sc[0];
            if (c < 1.0) c = 1.0;
            const double R = 0.5;
            const double loss = R * (sr[0] / c)
                              + (1.0 - R) * ((double)g_regsum / (double)NN);
            out[0] = (float)loss;
            g_ticket = 0;             // reset for next graph replay
        }
    }
}

extern "C" void kernel_launch(void* const* d_in, const int* in_sizes, int n_in,
                              void* d_out, int out_size)
{
    // Robust input mapping: pred has NN elements, target has 2*NN.
    int pred_idx = 0, tgt_idx = 1;
    if (n_in >= 2 && in_sizes[0] > in_sizes[1]) { pred_idx = 1; tgt_idx = 0; }
    const float* pred   = (const float*)d_in[pred_idx];
    const float* target = (const float*)d_in[tgt_idx];
    float* out = (float*)d_out;

    svm_compact_kernel<<<1, CTHREADS>>>(pred, target);
    svm_pair_kernel<<<GRID, THREADS>>>(pred, target, out);
}